// round 2
// baseline (speedup 1.0000x reference)
#include <cuda_runtime.h>
#include <cstdint>

#define NN 100000
#define NE 1600000
#define NR 8

// ---------------- scratch (static __device__, no allocation) ----------------
__device__ float    g_xw[(size_t)NR * NN * 64];   // [8,N,64] L0, reused [8,N,32] L1
__device__ float    g_h[(size_t)NN * 64];         // hidden activations
__device__ float    g_q[NR * NN];
__device__ float    g_k[NR * NN];
__device__ unsigned g_csr[NE];                    // packed: src | (rel<<20)
__device__ int      g_deg[NN];
__device__ int      g_start[NN];
__device__ int      g_cur[NN];
__device__ int      g_bsum[128];
__device__ float    g_wq0[NR * 64], g_wk0[NR * 64];
__device__ float    g_wq1[NR * 64], g_wk1[NR * 64];

// ---------------- CSR build ----------------
__global__ void zero_kernel() {
    int i = blockIdx.x * blockDim.x + threadIdx.x;
    if (i < NN) { g_deg[i] = 0; g_cur[i] = 0; }
}

// NOTE: edge_index / edge_type arrive as int32 (JAX x64 disabled).
__global__ void count_kernel(const int* __restrict__ ei) {
    int e = blockIdx.x * blockDim.x + threadIdx.x;
    if (e < NE) atomicAdd(&g_deg[ei[NE + e]], 1);
}

constexpr int SCAN_B = 1024;
constexpr int NB = (NN + SCAN_B - 1) / SCAN_B;  // 98

__global__ void scan1_kernel() {
    __shared__ int sh[SCAN_B];
    int i = blockIdx.x * SCAN_B + threadIdx.x;
    int v = (i < NN) ? g_deg[i] : 0;
    sh[threadIdx.x] = v;
    __syncthreads();
    for (int o = 1; o < SCAN_B; o <<= 1) {
        int t = (threadIdx.x >= o) ? sh[threadIdx.x - o] : 0;
        __syncthreads();
        sh[threadIdx.x] += t;
        __syncthreads();
    }
    if (i < NN) g_start[i] = sh[threadIdx.x] - v;  // exclusive
    if (threadIdx.x == SCAN_B - 1) g_bsum[blockIdx.x] = sh[SCAN_B - 1];
}

__global__ void scan2_kernel() {
    int s = 0;
    for (int b = 0; b < NB; b++) { int v = g_bsum[b]; g_bsum[b] = s; s += v; }
}

__global__ void scan3_kernel() {
    int i = blockIdx.x * SCAN_B + threadIdx.x;
    if (i < NN) g_start[i] += g_bsum[blockIdx.x];
}

__global__ void fill_kernel(const int* __restrict__ ei,
                            const int* __restrict__ et) {
    int e = blockIdx.x * blockDim.x + threadIdx.x;
    if (e >= NE) return;
    int s = ei[e];
    int d = ei[NE + e];
    int r = et[e];
    int pos = g_start[d] + atomicAdd(&g_cur[d], 1);
    g_csr[pos] = (unsigned)s | ((unsigned)r << 20);
}

// ---------------- WQ = W@Q, WK = W@K  (tiny) ----------------
template <bool L1>
__global__ void wqk_kernel(const float* __restrict__ W, const float* __restrict__ Q,
                           const float* __restrict__ K) {
    constexpr int OC = L1 ? 32 : 64;
    int idx = blockIdx.x * blockDim.x + threadIdx.x;  // r*64 + i
    if (idx >= NR * 64) return;
    const float* wrow = W + (size_t)idx * OC;
    float sq = 0.f, sk = 0.f;
    for (int o = 0; o < OC; o++) { float w = wrow[o]; sq += w * Q[o]; sk += w * K[o]; }
    (L1 ? g_wq1 : g_wq0)[idx] = sq;
    (L1 ? g_wk1 : g_wk0)[idx] = sk;
}

// ---------------- q[r,n] = feat[n] . WQ[r], k likewise (warp per node) ----------------
template <bool L1>
__global__ __launch_bounds__(256) void qk_kernel(const float* __restrict__ xin) {
    int gt = blockIdx.x * blockDim.x + threadIdx.x;
    int n = gt >> 5, lane = gt & 31;
    if (n >= NN) return;
    const float* feat = L1 ? g_h : xin;
    const float* wq = L1 ? g_wq1 : g_wq0;
    const float* wk = L1 ? g_wk1 : g_wk0;
    float2 xv = ((const float2*)(feat + (size_t)n * 64))[lane];
#pragma unroll
    for (int r = 0; r < NR; r++) {
        float2 a = ((const float2*)(wq + r * 64))[lane];
        float2 b = ((const float2*)(wk + r * 64))[lane];
        float sq = xv.x * a.x + xv.y * a.y;
        float sk = xv.x * b.x + xv.y * b.y;
#pragma unroll
        for (int o = 16; o > 0; o >>= 1) {
            sq += __shfl_xor_sync(0xffffffffu, sq, o);
            sk += __shfl_xor_sync(0xffffffffu, sk, o);
        }
        if (lane == 0) { g_q[r * NN + n] = sq; g_k[r * NN + n] = sk; }
    }
}

// ---------------- fp32 tiled GEMM: xw[r] = feat @ W[r] ----------------
constexpr int MT = 96;  // rows per block

template <bool L1>
__global__ __launch_bounds__(96) void gemm_kernel(const float* __restrict__ xin,
                                                  const float* __restrict__ W) {
    constexpr int OC = L1 ? 32 : 64;
    constexpr int CPT = L1 ? 4 : 8;  // cols per thread
    __shared__ __align__(16) float As[MT][68];  // m-major, padded
    __shared__ __align__(16) float Bs[64][OC];

    const float* X = L1 ? g_h : xin;
    int r = blockIdx.y;
    int m0 = blockIdx.x * MT;
    int tid = threadIdx.x;
    const float* Wr = W + (size_t)r * 64 * OC;

    for (int idx = tid; idx < 64 * OC / 4; idx += 96)
        ((float4*)Bs)[idx] = ((const float4*)Wr)[idx];

    for (int idx = tid; idx < MT * 16; idx += 96) {
        int mm = idx >> 4, k4 = idx & 15;
        int gm = m0 + mm;
        float4 v = (gm < NN) ? ((const float4*)(X + (size_t)gm * 64))[k4]
                             : make_float4(0.f, 0.f, 0.f, 0.f);
        *((float4*)&As[mm][k4 * 4]) = v;
    }
    __syncthreads();

    int tr = tid >> 3, tc = tid & 7;  // tr 0..11, tc 0..7
    float acc[8][CPT];
#pragma unroll
    for (int i = 0; i < 8; i++)
#pragma unroll
        for (int j = 0; j < CPT; j++) acc[i][j] = 0.f;

#pragma unroll 4
    for (int kq = 0; kq < 64; kq++) {
        float a[8];
#pragma unroll
        for (int i = 0; i < 8; i++) a[i] = As[tr + 12 * i][kq];
        float b[CPT];
        if constexpr (CPT == 8) {
            float4 b0 = *(const float4*)&Bs[kq][tc * 8];
            float4 b1 = *(const float4*)&Bs[kq][tc * 8 + 4];
            b[0] = b0.x; b[1] = b0.y; b[2] = b0.z; b[3] = b0.w;
            b[4] = b1.x; b[5] = b1.y; b[6] = b1.z; b[7] = b1.w;
        } else {
            float4 b0 = *(const float4*)&Bs[kq][tc * 4];
            b[0] = b0.x; b[1] = b0.y; b[2] = b0.z; b[3] = b0.w;
        }
#pragma unroll
        for (int i = 0; i < 8; i++)
#pragma unroll
            for (int j = 0; j < CPT; j++) acc[i][j] += a[i] * b[j];
    }

#pragma unroll
    for (int i = 0; i < 8; i++) {
        int gm = m0 + tr + 12 * i;
        if (gm < NN) {
            float* dst = g_xw + ((size_t)r * NN + gm) * OC + tc * CPT;
            *(float4*)dst = make_float4(acc[i][0], acc[i][1], acc[i][2], acc[i][3]);
            if constexpr (CPT == 8)
                *(float4*)(dst + 4) = make_float4(acc[i][4], acc[i][5], acc[i][6], acc[i][7]);
        }
    }
}

// ---------------- warp-per-node softmax + weighted aggregation ----------------
template <bool L1>
__global__ __launch_bounds__(256) void agg_kernel(const float* __restrict__ bias,
                                                  float* __restrict__ outp) {
    constexpr int OC = L1 ? 32 : 64;
    int gt = blockIdx.x * blockDim.x + threadIdx.x;
    int n = gt >> 5, lane = gt & 31;
    if (n >= NN) return;

    float qv[NR];
#pragma unroll
    for (int r = 0; r < NR; r++) qv[r] = g_q[r * NN + n];

    int s0 = g_start[n];
    int deg = g_deg[n];

    // pass 1: online (max, sum-exp) over incoming edges, lane-strided
    float m = -__int_as_float(0x7f800000);  // -inf
    float d = 0.f;
    for (int j = lane; j < deg; j += 32) {
        unsigned p = g_csr[s0 + j];
        int src = p & 0xFFFFF;
        int r = p >> 20;
        float al = qv[r] + g_k[r * NN + src];
        al = al > 0.f ? al : 0.2f * al;  // leaky_relu(0.2)
        float nm = fmaxf(m, al);
        d = d * (m == nm ? 1.f : __expf(m - nm)) + __expf(al - nm);
        m = nm;
    }
#pragma unroll
    for (int o = 16; o > 0; o >>= 1) {
        float om = __shfl_xor_sync(0xffffffffu, m, o);
        float od = __shfl_xor_sync(0xffffffffu, d, o);
        float nm = fmaxf(m, om);
        float w1 = (m == nm) ? 1.f : __expf(m - nm);
        float w2 = (om == nm) ? 1.f : __expf(om - nm);
        d = d * w1 + od * w2;
        m = nm;
    }
    float inv = 1.f / (d + 1e-16f);

    // pass 2: weighted gather-accumulate; whole warp cooperates per edge
    float acc0 = 0.f, acc1 = 0.f;
    for (int j = 0; j < deg; j++) {
        unsigned p = g_csr[s0 + j];  // broadcast load
        int src = p & 0xFFFFF;
        int r = p >> 20;
        float al = qv[r] + g_k[r * NN + src];
        al = al > 0.f ? al : 0.2f * al;
        float coef = __expf(al - m) * inv;
        const float* row = g_xw + ((size_t)r * NN + src) * OC;
        if constexpr (OC == 64) {
            float2 v = ((const float2*)row)[lane];
            acc0 += coef * v.x;
            acc1 += coef * v.y;
        } else {
            acc0 += coef * row[lane];
        }
    }

    if constexpr (OC == 64) {
        float o0 = acc0 + bias[2 * lane], o1 = acc1 + bias[2 * lane + 1];
        o0 = fmaxf(o0, 0.f);  // layer-0 relu
        o1 = fmaxf(o1, 0.f);
        ((float2*)(g_h + (size_t)n * 64))[lane] = make_float2(o0, o1);
    } else {
        outp[(size_t)n * 32 + lane] = acc0 + bias[lane];
    }
}

// ---------------- launch ----------------
extern "C" void kernel_launch(void* const* d_in, const int* in_sizes, int n_in,
                              void* d_out, int out_size) {
    const float* x  = (const float*)d_in[0];
    const int*   ei = (const int*)d_in[1];   // int32! (JAX x64 disabled)
    const int*   et = (const int*)d_in[2];   // int32!
    const float* W0 = (const float*)d_in[3];
    const float* Q0 = (const float*)d_in[4];
    const float* K0 = (const float*)d_in[5];
    const float* b0 = (const float*)d_in[6];
    const float* W1 = (const float*)d_in[7];
    const float* Q1 = (const float*)d_in[8];
    const float* K1 = (const float*)d_in[9];
    const float* b1 = (const float*)d_in[10];
    float* out = (float*)d_out;

    // CSR build (shared by both layers)
    zero_kernel<<<(NN + 255) / 256, 256>>>();
    count_kernel<<<(NE + 255) / 256, 256>>>(ei);
    scan1_kernel<<<NB, SCAN_B>>>();
    scan2_kernel<<<1, 1>>>();
    scan3_kernel<<<NB, SCAN_B>>>();
    fill_kernel<<<(NE + 255) / 256, 256>>>(ei, et);

    // fused attention projections
    wqk_kernel<false><<<2, 256>>>(W0, Q0, K0);
    wqk_kernel<true><<<2, 256>>>(W1, Q1, K1);

    dim3 ggrid((NN + MT - 1) / MT, NR);

    // layer 0
    qk_kernel<false><<<(NN * 32 + 255) / 256, 256>>>(x);
    gemm_kernel<false><<<ggrid, 96>>>(x, W0);
    agg_kernel<false><<<(NN * 32 + 255) / 256, 256>>>(b0, out);

    // layer 1
    qk_kernel<true><<<(NN * 32 + 255) / 256, 256>>>(x);
    gemm_kernel<true><<<ggrid, 96>>>(x, W1);
    agg_kernel<true><<<(NN * 32 + 255) / 256, 256>>>(b1, out);
}